// round 10
// baseline (speedup 1.0000x reference)
#include <cuda_runtime.h>
#include <cuda_fp16.h>

// Problem constants
#define Bz 16
#define Nn 5000
#define Ff 64
#define Hh 32
#define Ee 160000
#define ETOT (Ee + Nn)         // edges + self loops = 165000
#define Kdim (Nn * Hh)         // 160000
#define NHID 512
#define NACT 16
#define KSPLIT 148
#define CHUNK 1088             // k-rows per block = 34 nodes (multiple of 32)
#define CH 16                  // k-rows per TMA stage (32 KB contiguous)
#define NST 4                  // ring stages
#define STAGE_BYTES (CH * NHID * 4)   // 32768

// -------- scratch (device globals; no allocation allowed) --------
__device__ int    g_is64;
__device__ int    g_deg[Nn];
__device__ int    g_cursor[Nn];
__device__ int    g_off[Nn + 1];
__device__ float  g_dinv[Nn];
__device__ int    g_srcs[ETOT];
__device__ float  g_nrms[ETOT];
__device__ __half g_xw1[Bz * Nn * Hh];   // 5.12 MB
__device__ __half g_xw2[Bz * Nn * Hh];   // 5.12 MB
__device__ float  g_hid[Bz * NHID];      // MLP hidden partials

__device__ __forceinline__ int edge_at(const void* ei, int idx) {
    if (g_is64) return (int)((const long long*)ei)[idx];
    return ((const int*)ei)[idx];
}

__device__ __forceinline__ unsigned smem_u32(const void* p) {
    unsigned a;
    asm("{ .reg .u64 t; cvta.to.shared.u64 t, %1; cvt.u32.u64 %0, t; }"
        : "=r"(a) : "l"(p));
    return a;
}

__device__ __forceinline__ void mbar_wait_parity(unsigned mbar, unsigned parity) {
    asm volatile(
        "{\n\t.reg .pred P;\n"
        "LW_%=:\n\t"
        "mbarrier.try_wait.parity.acquire.cta.shared::cta.b64 P, [%0], %1, 0x989680;\n\t"
        "@P bra LD_%=;\n\t"
        "bra LW_%=;\n"
        "LD_%=:\n\t}"
        :: "r"(mbar), "r"(parity) : "memory");
}

// ================= setup =================

__global__ void init_k(const unsigned int* __restrict__ ei) {
    int i = blockIdx.x * blockDim.x + threadIdx.x;
    if (i == 0) {
        int all0 = 1;
        for (int k = 0; k < 64; k++)
            if (ei[2 * k + 1] != 0u) { all0 = 0; break; }
        g_is64 = all0;
    }
    if (i < Nn) { g_deg[i] = 1; g_cursor[i] = 0; }
    if (i < Bz * NHID) g_hid[i] = 0.0f;
}

__global__ void hist_k(const void* __restrict__ ei) {
    int e = blockIdx.x * blockDim.x + threadIdx.x;
    if (e < Ee) atomicAdd(&g_deg[edge_at(ei, Ee + e)], 1);
}

// single block: dinv + exclusive scan of degrees (warp-shuffle based)
__global__ void scan_k() {
    __shared__ int wsum[32];
    int t = threadIdx.x, lane = t & 31, wid = t >> 5;
    const int CHD = 5;
    int base = t * CHD;
    int d[CHD];
    int local = 0;
#pragma unroll
    for (int j = 0; j < CHD; j++) {
        int idx = base + j;
        d[j] = (idx < Nn) ? g_deg[idx] : 0;
        local += d[j];
    }
    int incl = local;
#pragma unroll
    for (int off = 1; off < 32; off <<= 1) {
        int v = __shfl_up_sync(0xffffffffu, incl, off);
        if (lane >= off) incl += v;
    }
    if (lane == 31) wsum[wid] = incl;
    __syncthreads();
    if (wid == 0) {
        int iv = wsum[lane];
#pragma unroll
        for (int off = 1; off < 32; off <<= 1) {
            int u = __shfl_up_sync(0xffffffffu, iv, off);
            if (lane >= off) iv += u;
        }
        wsum[lane] = iv;
    }
    __syncthreads();
    int excl = (wid ? wsum[wid - 1] : 0) + (incl - local);
#pragma unroll
    for (int j = 0; j < CHD; j++) {
        int idx = base + j;
        if (idx < Nn) {
            g_off[idx] = excl;
            excl += d[j];
            g_dinv[idx] = rsqrtf((float)d[j]);
        }
    }
    if (t == 1023) g_off[Nn] = wsum[31];
}

__global__ void scatter_k(const void* __restrict__ ei) {
    int i = blockIdx.x * blockDim.x + threadIdx.x;
    if (i >= ETOT) return;
    int s, d;
    if (i < Ee) { s = edge_at(ei, i); d = edge_at(ei, Ee + i); }
    else        { s = d = i - Ee; }
    float nm = g_dinv[s] * g_dinv[d];
    int pos = g_off[d] + atomicAdd(&g_cursor[d], 1);
    g_srcs[pos] = s;
    g_nrms[pos] = nm;
}

// ============ layer1 GEMM: xw1[r,32] = feat[r,64] @ W1, fp16 out ============
__global__ __launch_bounds__(256) void gemm1_k(
    const float* __restrict__ X, const float* __restrict__ W,
    __half* __restrict__ Y)
{
    const int F = Ff;
    __shared__ float sx[64 * Ff];
    __shared__ float sw[Ff * 32];
    int tid = threadIdx.x;
    for (int i = tid; i < F * 32; i += 256) sw[i] = W[i];
    long long r0 = (long long)blockIdx.x * 64;
    for (int i = tid; i < 64 * F; i += 256) {
        int r = i >> 6, c = i & 63;
        sx[r * F + c] = X[(r0 + r) * F + c];
    }
    __syncthreads();
    int h = tid & 31;
    int g = tid >> 5;
    float acc[8] = {0.f, 0.f, 0.f, 0.f, 0.f, 0.f, 0.f, 0.f};
    for (int f = 0; f < F; f++) {
        float w = sw[f * 32 + h];
#pragma unroll
        for (int i = 0; i < 8; i++)
            acc[i] = fmaf(sx[(g * 8 + i) * F + f], w, acc[i]);
    }
#pragma unroll
    for (int i = 0; i < 8; i++)
        Y[(r0 + g * 8 + i) * 32 + h] = __float2half(acc[i]);
}

// ===== agg1 fused with layer2 transform: ILP-8 gathers, 256 thr, grid (Nn,2) =====
__global__ __launch_bounds__(256) void agg1_fuse_k(
    const __half* __restrict__ xw, const float* __restrict__ b1,
    const float* __restrict__ W2, __half* __restrict__ out2)
{
    __shared__ float sW2[32 * 32];
    int tid = threadIdx.x;
    for (int i = tid; i < 1024; i += 256) sW2[i] = W2[i];
    __syncthreads();

    int n = blockIdx.x;
    int b = blockIdx.y * 8 + (tid >> 5);
    int lane = tid & 31;
    int beg = g_off[n], end = g_off[n + 1];
    const __half* xb = xw + (size_t)b * (Nn * Hh);

    float a[8] = {0.f, 0.f, 0.f, 0.f, 0.f, 0.f, 0.f, 0.f};
    int e = beg;
    for (; e + 8 <= end; e += 8) {
        int   s[8];
        float m[8];
#pragma unroll
        for (int q = 0; q < 8; q++) { s[q] = g_srcs[e + q]; m[q] = g_nrms[e + q]; }
#pragma unroll
        for (int q = 0; q < 8; q++)
            a[q] = fmaf(m[q], __half2float(xb[s[q] * 32 + lane]), a[q]);
    }
    for (; e < end; e++)
        a[0] = fmaf(g_nrms[e], __half2float(xb[g_srcs[e] * 32 + lane]), a[0]);
    float h = ((a[0] + a[1]) + (a[2] + a[3])) + ((a[4] + a[5]) + (a[6] + a[7]));
    h = fmaxf(h + b1[lane], 0.0f);

    float o = 0.f;
#pragma unroll
    for (int f = 0; f < 32; f++) {
        float hf = __shfl_sync(0xffffffffu, h, f);
        o = fmaf(hf, sW2[f * 32 + lane], o);
    }
    out2[((size_t)b * Nn + n) * 32 + lane] = __float2half(o);
}

// ===== big MLP GEMM with FUSED agg2 in the staging step =====
// Block owns k-rows [k0,k0+1088) = 34 nodes. Per 128-row tile (4 nodes),
// the staging step COMPUTES h2 = relu(agg(xw2)+b2) for 4 nodes x 16 batches
// directly into smem (sbat), overlapping L2 gathers with TMA weight streaming.
__global__ __launch_bounds__(512) void mlp1_k(
    const __half* __restrict__ xw2, const float* __restrict__ b2,
    const float* __restrict__ Wp1)
{
    extern __shared__ __align__(16) unsigned char dsm[];
    float* wbuf = (float*)dsm;                               // NST*CH*512 floats
    unsigned long long* sbat =
        (unsigned long long*)(dsm + NST * STAGE_BYTES);      // [128][8] = float[128][16]
    float* sbatf = (float*)sbat;
    unsigned mbar0 = smem_u32(dsm + NST * STAGE_BYTES + 128 * 8 * 8);
    unsigned wbuf0 = smem_u32(dsm);

    int tid = threadIdx.x;
    int wid = tid >> 5, lane = tid & 31;
    int kg = tid >> 7;                    // k-group 0..3 (rows ≡ kg mod 4)
    int c4 = (tid & 127) * 4;             // columns c4..c4+3
    int k0 = blockIdx.x * CHUNK;
    int k1 = min(k0 + CHUNK, Kdim);
    int nch = (k1 - k0 + CH - 1) / CH;

    if (tid == 0) {
#pragma unroll
        for (int s = 0; s < NST; s++)
            asm volatile("mbarrier.init.shared.b64 [%0], 1;"
                         :: "r"(mbar0 + s * 8) : "memory");
        asm volatile("fence.proxy.async.shared::cta;" ::: "memory");
    }
    __syncthreads();

#define ISSUE_STAGE(cc)                                                         \
    do {                                                                        \
        int _c = (cc);                                                          \
        if (_c < nch && tid == 0) {                                             \
            unsigned _mb = mbar0 + (_c & (NST - 1)) * 8;                        \
            asm volatile(                                                       \
                "mbarrier.arrive.expect_tx.shared.b64 _, [%0], %1;"             \
                :: "r"(_mb), "r"((unsigned)STAGE_BYTES) : "memory");            \
            unsigned _dst = wbuf0 + (_c & (NST - 1)) * STAGE_BYTES;             \
            const float* _src = Wp1 + (size_t)(k0 + _c * CH) * NHID;            \
            asm volatile(                                                       \
                "cp.async.bulk.shared::cta.global.mbarrier::complete_tx::bytes "\
                "[%0], [%1], %2, [%3];"                                         \
                :: "r"(_dst), "l"(_src), "r"((unsigned)STAGE_BYTES), "r"(_mb)   \
                : "memory");                                                    \
        }                                                                       \
    } while (0)

    unsigned long long acc[4][8];         // [col][batch-pair]
#pragma unroll
    for (int c = 0; c < 4; c++)
#pragma unroll
        for (int p = 0; p < 8; p++) acc[c][p] = 0ull;

    ISSUE_STAGE(0);
    ISSUE_STAGE(1);
    ISSUE_STAGE(2);

    float bias = b2[lane];

    for (int c = 0; c < nch; c++) {
        int kbase = k0 + c * CH;

        if ((c & 7) == 0) {
            // FUSED agg2: compute h2 for the 4 nodes of tile [kbase, kbase+128)
            // 64 (node,batch) tasks; warp does tasks wid, wid+16, wid+32, wid+48.
            int ntile0 = kbase >> 5;      // kbase is a multiple of 32
#pragma unroll
            for (int i = 0; i < 4; i++) {
                int task = wid + 16 * i;  // 0..63
                int nn = task >> 4;       // tile-local node 0..3
                int b  = task & 15;       // batch
                int n  = ntile0 + nn;
                float val = 0.0f;
                if (n < Nn) {
                    int beg = g_off[n], end = g_off[n + 1];
                    const __half* xb = xw2 + (size_t)b * (Nn * Hh);
                    float a0 = 0.f, a1 = 0.f, a2 = 0.f, a3 = 0.f;
                    int e = beg;
                    for (; e + 4 <= end; e += 4) {
                        int   s0 = g_srcs[e],     s1 = g_srcs[e + 1];
                        int   s2 = g_srcs[e + 2], s3 = g_srcs[e + 3];
                        float m0 = g_nrms[e],     m1 = g_nrms[e + 1];
                        float m2 = g_nrms[e + 2], m3 = g_nrms[e + 3];
                        a0 = fmaf(m0, __half2float(xb[s0 * 32 + lane]), a0);
                        a1 = fmaf(m1, __half2float(xb[s1 * 32 + lane]), a1);
                        a2 = fmaf(m2, __half2float(xb[s2 * 32 + lane]), a2);
                        a3 = fmaf(m3, __half2float(xb[s3 * 32 + lane]), a3);
                    }
                    for (; e < end; e++)
                        a0 = fmaf(g_nrms[e],
                                  __half2float(xb[g_srcs[e] * 32 + lane]), a0);
                    val = fmaxf((a0 + a1) + (a2 + a3) + bias, 0.0f);
                }
                // sbat as float[128][16]: row kk = nn*32+lane, col = batch
                sbatf[(nn * 32 + lane) * 16 + b] = val;
            }
            __syncthreads();
        }

        mbar_wait_parity(mbar0 + (c & (NST - 1)) * 8, (unsigned)((c >> 2) & 1));

        const float* wst = wbuf + (c & (NST - 1)) * (CH * NHID);
#pragma unroll
        for (int rr = 0; rr < 4; rr++) {
            int r = kg + rr * 4;
            float4 w = *(const float4*)(wst + r * NHID + c4);
            unsigned long long wd[4];
            asm("mov.b64 %0, {%1, %1};" : "=l"(wd[0]) : "r"(__float_as_uint(w.x)));
            asm("mov.b64 %0, {%1, %1};" : "=l"(wd[1]) : "r"(__float_as_uint(w.y)));
            asm("mov.b64 %0, {%1, %1};" : "=l"(wd[2]) : "r"(__float_as_uint(w.z)));
            asm("mov.b64 %0, {%1, %1};" : "=l"(wd[3]) : "r"(__float_as_uint(w.w)));
            int kk = (c & 7) * CH + r;
            const ulonglong2* f2 = (const ulonglong2*)(sbat + kk * 8);
#pragma unroll
            for (int q = 0; q < 4; q++) {
                ulonglong2 f = f2[q];
#pragma unroll
                for (int cc = 0; cc < 4; cc++) {
                    asm("fma.rn.f32x2 %0, %1, %2, %0;"
                        : "+l"(acc[cc][2 * q])     : "l"(wd[cc]), "l"(f.x));
                    asm("fma.rn.f32x2 %0, %1, %2, %0;"
                        : "+l"(acc[cc][2 * q + 1]) : "l"(wd[cc]), "l"(f.y));
                }
            }
        }
        __syncthreads();
        ISSUE_STAGE(c + 3);
    }
#undef ISSUE_STAGE

#pragma unroll
    for (int cc = 0; cc < 4; cc++)
#pragma unroll
        for (int p = 0; p < 8; p++) {
            float2 v = *(float2*)&acc[cc][p];
            atomicAdd(&g_hid[(2 * p)     * NHID + c4 + cc], v.x);
            atomicAdd(&g_hid[(2 * p + 1) * NHID + c4 + cc], v.y);
        }
}

// ===== final: relu(hid+bp1) @ Wp2 + bp2, one block per batch =====
__global__ __launch_bounds__(512) void mlp2_k(
    const float* __restrict__ bp1, const float* __restrict__ Wp2,
    const float* __restrict__ bp2, float* __restrict__ out)
{
    __shared__ float part[16][NACT];
    int b = blockIdx.x;
    int j = threadIdx.x;
    int wid = j >> 5, lane = j & 31;
    float hv = fmaxf(g_hid[b * NHID + j] + bp1[j], 0.0f);
    float acc[NACT];
#pragma unroll
    for (int a = 0; a < NACT; a++) acc[a] = hv * Wp2[j * NACT + a];
#pragma unroll
    for (int off = 16; off; off >>= 1)
#pragma unroll
        for (int a = 0; a < NACT; a++)
            acc[a] += __shfl_down_sync(0xffffffffu, acc[a], off);
    if (lane == 0)
#pragma unroll
        for (int a = 0; a < NACT; a++) part[wid][a] = acc[a];
    __syncthreads();
    if (j < NACT) {
        float s = bp2[j];
#pragma unroll
        for (int w = 0; w < 16; w++) s += part[w][j];
        out[b * NACT + j] = s;
    }
}

// ================= launch =================
extern "C" void kernel_launch(void* const* d_in, const int* in_sizes, int n_in,
                              void* d_out, int out_size)
{
    const float* features = (const float*)d_in[0];
    const void*  edge     = d_in[1];
    const float* W1  = (const float*)d_in[2];
    const float* b1  = (const float*)d_in[3];
    const float* W2  = (const float*)d_in[4];
    const float* b2  = (const float*)d_in[5];
    const float* Wp1 = (const float*)d_in[6];
    const float* bp1 = (const float*)d_in[7];
    const float* Wp2 = (const float*)d_in[8];
    const float* bp2 = (const float*)d_in[9];
    float* out = (float*)d_out;

    __half* xw1; cudaGetSymbolAddress((void**)&xw1, g_xw1);
    __half* xw2; cudaGetSymbolAddress((void**)&xw2, g_xw2);

    init_k<<<(Bz * NHID + 255) / 256, 256>>>((const unsigned int*)edge);
    hist_k<<<(Ee + 255) / 256, 256>>>(edge);
    scan_k<<<1, 1024>>>();
    scatter_k<<<(ETOT + 255) / 256, 256>>>(edge);

    gemm1_k<<<(Bz * Nn) / 64, 256>>>(features, W1, xw1);
    dim3 agrid(Nn, 2);
    agg1_fuse_k<<<agrid, 256>>>(xw1, b1, W2, xw2);

    size_t smem = (size_t)NST * STAGE_BYTES + 128 * 8 * 8 + 64;  // 131072+8192+64
    cudaFuncSetAttribute(mlp1_k, cudaFuncAttributeMaxDynamicSharedMemorySize,
                         (int)smem);
    mlp1_k<<<KSPLIT, 512, smem>>>(xw2, b2, Wp1);
    mlp2_k<<<Bz, 512>>>(bp1, Wp2, bp2, out);
}